// round 1
// baseline (speedup 1.0000x reference)
#include <cuda_runtime.h>
#include <math.h>

#define N_TOK 8192
#define D_DIM 1024
#define E_NUM 8
#define H_DIM 4096
#define CAP   8192          // per-expert token capacity (<= N_TOK)
#define PAIRS 16384         // total (token, expert) pairs is exactly 2*N_TOK

// ---- scratch (device globals; no allocation allowed) ----
__device__ int   g_cnt[E_NUM];
__device__ int   g_off[E_NUM];
__device__ int   g_tok[E_NUM * CAP];
__device__ float g_wt [E_NUM * CAP];
__device__ float g_h  [(size_t)PAIRS * H_DIM];   // 268 MB hidden activations

// ---------------------------------------------------------------------------
// zero: expert counts + output buffer
// ---------------------------------------------------------------------------
__global__ void zero_kernel(float* __restrict__ out, int n) {
    int i = blockIdx.x * blockDim.x + threadIdx.x;
    if (i < E_NUM) g_cnt[i] = 0;
    for (; i < n; i += gridDim.x * blockDim.x) out[i] = 0.0f;
}

// ---------------------------------------------------------------------------
// router: one warp per token. logits = x @ Wr + br, top-2, softmax over the 2.
// ---------------------------------------------------------------------------
__global__ void router_kernel(const float* __restrict__ x,
                              const float* __restrict__ Wr,
                              const float* __restrict__ br) {
    int warp = (blockIdx.x * blockDim.x + threadIdx.x) >> 5;
    int lane = threadIdx.x & 31;
    if (warp >= N_TOK) return;

    const float* xr = x + (size_t)warp * D_DIM;
    float acc[8];
#pragma unroll
    for (int e = 0; e < 8; e++) acc[e] = 0.0f;

    for (int d = lane; d < D_DIM; d += 32) {
        float xv = xr[d];
        const float4* w4 = (const float4*)(Wr + (size_t)d * E_NUM);
        float4 a = w4[0], b = w4[1];
        acc[0] += xv * a.x; acc[1] += xv * a.y;
        acc[2] += xv * a.z; acc[3] += xv * a.w;
        acc[4] += xv * b.x; acc[5] += xv * b.y;
        acc[6] += xv * b.z; acc[7] += xv * b.w;
    }
#pragma unroll
    for (int off = 16; off > 0; off >>= 1) {
#pragma unroll
        for (int e = 0; e < 8; e++)
            acc[e] += __shfl_down_sync(0xffffffffu, acc[e], off);
    }

    if (lane == 0) {
        float lg[8];
#pragma unroll
        for (int e = 0; e < 8; e++) lg[e] = acc[e] + br[e];

        // top-2 with first-occurrence tie-break (matches lax.top_k)
        int e0 = 0;
#pragma unroll
        for (int e = 1; e < 8; e++) if (lg[e] > lg[e0]) e0 = e;
        int e1 = (e0 == 0) ? 1 : 0;
#pragma unroll
        for (int e = 0; e < 8; e++)
            if (e != e0 && e != e1 && lg[e] > lg[e1]) e1 = e;

        // softmax over {lg[e0], lg[e1]}; all masked entries underflow to 0
        float z  = __expf(lg[e1] - lg[e0]);
        float w0 = 1.0f / (1.0f + z);
        float w1 = z * w0;

        int p0 = atomicAdd(&g_cnt[e0], 1);
        g_tok[e0 * CAP + p0] = warp;
        g_wt [e0 * CAP + p0] = w0;
        int p1 = atomicAdd(&g_cnt[e1], 1);
        g_tok[e1 * CAP + p1] = warp;
        g_wt [e1 * CAP + p1] = w1;
    }
}

// ---------------------------------------------------------------------------
// exclusive prefix offsets (8 experts — single thread is fine)
// ---------------------------------------------------------------------------
__global__ void offsets_kernel() {
    if (threadIdx.x == 0 && blockIdx.x == 0) {
        int acc = 0;
#pragma unroll
        for (int e = 0; e < E_NUM; e++) {
            g_off[e] = acc;
            acc += g_cnt[e];
        }
    }
}

// ---------------------------------------------------------------------------
// grouped GEMM, 128x128 tile, BK=8, 256 threads, 8x8 micro-tile.
// PHASE 1: A = gathered x rows [Ne, 1024], B = W1[e] [1024,4096],
//          C = relu(.+b1) -> g_h rows (g_off[e]+r)
// PHASE 2: A = g_h rows [Ne, 4096], B = W2[e] [4096,1024],
//          C = atomicAdd(out[token], w*(.+b2))
// ---------------------------------------------------------------------------
template <int PHASE, int K, int N>
__global__ __launch_bounds__(256)
void moe_gemm(const float* __restrict__ X,     // phase1: x, phase2: unused
              const float* __restrict__ Wgt,   // [E][K][N] row-major
              const float* __restrict__ bias,  // [E][N]
              float* __restrict__ out)         // phase2 only
{
    const int e  = blockIdx.z;
    const int Ne = g_cnt[e];
    const int m0 = blockIdx.y * 128;
    if (m0 >= Ne) return;
    const int n0 = blockIdx.x * 128;

    const float* Bmat = Wgt + (size_t)e * K * N;

    __shared__ float As[8][128];
    __shared__ float Bs[8][128];

    const int tid  = threadIdx.x;
    const int arow = tid >> 1;          // 0..127
    const int acol = (tid & 1) * 4;     // 0 or 4
    const int brow = tid >> 5;          // 0..7
    const int bcol = (tid & 31) * 4;    // 0..124

    const int  grow   = m0 + arow;
    const bool avalid = (grow < Ne);

    const float* Aptr;
    if (PHASE == 1) {
        int tok = avalid ? g_tok[e * CAP + grow] : 0;
        Aptr = X + (size_t)tok * K;
    } else {
        int hrow = g_off[e] + (avalid ? grow : 0);
        Aptr = g_h + (size_t)hrow * K;
    }

    float acc[8][8];
#pragma unroll
    for (int i = 0; i < 8; i++)
#pragma unroll
        for (int j = 0; j < 8; j++) acc[i][j] = 0.0f;

    const int ty = tid >> 4;   // 0..15
    const int tx = tid & 15;   // 0..15

    for (int k0 = 0; k0 < K; k0 += 8) {
        float4 av = avalid ? *(const float4*)(Aptr + k0 + acol)
                           : make_float4(0.f, 0.f, 0.f, 0.f);
        As[acol + 0][arow] = av.x;
        As[acol + 1][arow] = av.y;
        As[acol + 2][arow] = av.z;
        As[acol + 3][arow] = av.w;
        *(float4*)&Bs[brow][bcol] =
            *(const float4*)(Bmat + (size_t)(k0 + brow) * N + n0 + bcol);
        __syncthreads();

#pragma unroll
        for (int kk = 0; kk < 8; kk++) {
            float a[8], b[8];
            *(float4*)(a)     = *(const float4*)&As[kk][ty * 8];
            *(float4*)(a + 4) = *(const float4*)&As[kk][ty * 8 + 4];
            *(float4*)(b)     = *(const float4*)&Bs[kk][tx * 8];
            *(float4*)(b + 4) = *(const float4*)&Bs[kk][tx * 8 + 4];
#pragma unroll
            for (int i = 0; i < 8; i++)
#pragma unroll
                for (int j = 0; j < 8; j++)
                    acc[i][j] = fmaf(a[i], b[j], acc[i][j]);
        }
        __syncthreads();
    }

    const float* brow_ptr = bias + (size_t)e * N + n0 + tx * 8;

    if (PHASE == 1) {
        const int base = g_off[e];
#pragma unroll
        for (int i = 0; i < 8; i++) {
            int r = m0 + ty * 8 + i;
            if (r < Ne) {
                float* hr = g_h + (size_t)(base + r) * N + n0 + tx * 8;
#pragma unroll
                for (int j = 0; j < 8; j++) {
                    float v = acc[i][j] + brow_ptr[j];
                    hr[j] = v > 0.0f ? v : 0.0f;
                }
            }
        }
    } else {
#pragma unroll
        for (int i = 0; i < 8; i++) {
            int r = m0 + ty * 8 + i;
            if (r < Ne) {
                int   tok = g_tok[e * CAP + r];
                float w   = g_wt [e * CAP + r];
                float* orow = out + (size_t)tok * N + n0 + tx * 8;
#pragma unroll
                for (int j = 0; j < 8; j++)
                    atomicAdd(&orow[j], w * (acc[i][j] + brow_ptr[j]));
            }
        }
    }
}

// ---------------------------------------------------------------------------
extern "C" void kernel_launch(void* const* d_in, const int* in_sizes, int n_in,
                              void* d_out, int out_size) {
    const float* x  = (const float*)d_in[0];
    const float* Wr = (const float*)d_in[1];
    const float* br = (const float*)d_in[2];
    const float* W1 = (const float*)d_in[3];
    const float* b1 = (const float*)d_in[4];
    const float* W2 = (const float*)d_in[5];
    const float* b2 = (const float*)d_in[6];
    float* out = (float*)d_out;

    // 1) zero counts + output
    zero_kernel<<<1024, 256>>>(out, out_size);

    // 2) router: one warp per token
    router_kernel<<<(N_TOK * 32 + 255) / 256, 256>>>(x, Wr, br);

    // 3) offsets
    offsets_kernel<<<1, 32>>>();

    // 4) GEMM1: [Ne,1024] x [1024,4096] -> relu -> g_h
    {
        dim3 grid(H_DIM / 128, CAP / 128, E_NUM);
        moe_gemm<1, D_DIM, H_DIM><<<grid, 256>>>(x, W1, b1, nullptr);
    }

    // 5) GEMM2: [Ne,4096] x [4096,1024] -> w*(.+b2) atomically into out
    {
        dim3 grid(D_DIM / 128, CAP / 128, E_NUM);
        moe_gemm<2, H_DIM, D_DIM><<<grid, 256>>>(nullptr, W2, b2, out);
    }
}

// round 3
// speedup vs baseline: 2.5222x; 2.5222x over previous
#include <cuda_runtime.h>
#include <cuda_bf16.h>
#include <math.h>
#include <stdint.h>

#define N_TOK 8192
#define D_DIM 1024
#define E_NUM 8
#define H_DIM 4096
#define CAP   8192
#define PAIRS 16384

#define TM 128
#define TN 128
#define TK 32            // bf16 elems per k-chunk (64 bytes per row)
#define ROWB 80          // padded SMEM row bytes (64 data + 16 pad)
#define AH 0
#define AL 10240
#define BH 20480
#define BL 30720
#define STG 40960
#define GEMM_SMEM (2 * STG)

// ---------------- device scratch ----------------
__device__ int   g_cnt[E_NUM];
__device__ int   g_off[E_NUM];
__device__ int   g_tok[E_NUM * CAP];
__device__ int   g_tslot[2 * N_TOK];   // e*CAP + p for each token's 2 experts
__device__ float g_tw  [2 * N_TOK];

__device__ __nv_bfloat16 g_xh[(size_t)N_TOK * D_DIM];
__device__ __nv_bfloat16 g_xl[(size_t)N_TOK * D_DIM];
__device__ __nv_bfloat16 g_hh[(size_t)PAIRS * H_DIM];
__device__ __nv_bfloat16 g_hl[(size_t)PAIRS * H_DIM];
__device__ float         g_y [(size_t)PAIRS * D_DIM];
// packed weights, [E][N][K] row-major bf16 (transposed from [E][K][N] fp32)
__device__ __nv_bfloat16 g_B1h[(size_t)E_NUM * H_DIM * D_DIM];
__device__ __nv_bfloat16 g_B1l[(size_t)E_NUM * H_DIM * D_DIM];
__device__ __nv_bfloat16 g_B2h[(size_t)E_NUM * D_DIM * H_DIM];
__device__ __nv_bfloat16 g_B2l[(size_t)E_NUM * D_DIM * H_DIM];

// ---------------- helpers ----------------
__device__ __forceinline__ uint32_t smem_u32(const void* p) {
    return (uint32_t)__cvta_generic_to_shared(p);
}
#define CP16(dst, src) \
    asm volatile("cp.async.cg.shared.global [%0], [%1], 16;" :: "r"(dst), "l"(src) : "memory")
#define CP_COMMIT() asm volatile("cp.async.commit_group;" ::: "memory")

__device__ __forceinline__ void ldsm4(uint32_t* r, uint32_t addr) {
    asm volatile("ldmatrix.sync.aligned.m8n8.x4.shared.b16 {%0,%1,%2,%3}, [%4];"
        : "=r"(r[0]), "=r"(r[1]), "=r"(r[2]), "=r"(r[3]) : "r"(addr));
}
__device__ __forceinline__ void mma_bf16(float* c, const uint32_t* a, const uint32_t* b) {
    asm volatile("mma.sync.aligned.m16n8k16.row.col.f32.bf16.bf16.f32 "
        "{%0,%1,%2,%3}, {%4,%5,%6,%7}, {%8,%9}, {%0,%1,%2,%3};"
        : "+f"(c[0]), "+f"(c[1]), "+f"(c[2]), "+f"(c[3])
        : "r"(a[0]), "r"(a[1]), "r"(a[2]), "r"(a[3]), "r"(b[0]), "r"(b[1]));
}

// ---------------- small kernels ----------------
__global__ void zero_cnt_kernel() {
    if (threadIdx.x < E_NUM) g_cnt[threadIdx.x] = 0;
}

__global__ void cvt_x_kernel(const float* __restrict__ x) {
    size_t stride = (size_t)gridDim.x * blockDim.x;
    size_t n = (size_t)N_TOK * D_DIM;
    for (size_t i = (size_t)blockIdx.x * blockDim.x + threadIdx.x; i < n; i += stride) {
        float v = x[i];
        __nv_bfloat16 h = __float2bfloat16(v);
        g_xh[i] = h;
        g_xl[i] = __float2bfloat16(v - __bfloat162float(h));
    }
}

// W[e][K][N] fp32 -> P[e][N][K] bf16 hi/lo (32x32 tile transpose)
__global__ __launch_bounds__(256)
void pack_w_kernel(const float* __restrict__ W, __nv_bfloat16* __restrict__ Ph,
                   __nv_bfloat16* __restrict__ Pl, int K, int N) {
    __shared__ float s[32][33];
    const int k0 = blockIdx.x * 32, n0 = blockIdx.y * 32, e = blockIdx.z;
    const int tid = threadIdx.x;
    const int kk = tid >> 5, nn = tid & 31;
#pragma unroll
    for (int i = 0; i < 4; i++)
        s[kk + i * 8][nn] = W[((size_t)e * K + k0 + kk + i * 8) * N + n0 + nn];
    __syncthreads();
    const int n_r = tid >> 4;          // 0..15
    const int kp  = (tid & 15) * 2;
#pragma unroll
    for (int i = 0; i < 2; i++) {
        int nr = n_r + i * 16;
        float v0 = s[kp][nr], v1 = s[kp + 1][nr];
        __nv_bfloat16 h0 = __float2bfloat16(v0), h1 = __float2bfloat16(v1);
        __nv_bfloat162 hp; hp.x = h0; hp.y = h1;
        __nv_bfloat162 lp;
        lp.x = __float2bfloat16(v0 - __bfloat162float(h0));
        lp.y = __float2bfloat16(v1 - __bfloat162float(h1));
        size_t o = ((size_t)e * N + n0 + nr) * K + k0 + kp;
        *(__nv_bfloat162*)(Ph + o) = hp;
        *(__nv_bfloat162*)(Pl + o) = lp;
    }
}

__global__ void router_kernel(const float* __restrict__ x,
                              const float* __restrict__ Wr,
                              const float* __restrict__ br) {
    int warp = (blockIdx.x * blockDim.x + threadIdx.x) >> 5;
    int lane = threadIdx.x & 31;
    if (warp >= N_TOK) return;
    const float* xr = x + (size_t)warp * D_DIM;
    float acc[8];
#pragma unroll
    for (int e = 0; e < 8; e++) acc[e] = 0.0f;
    for (int d = lane; d < D_DIM; d += 32) {
        float xv = xr[d];
        const float4* w4 = (const float4*)(Wr + (size_t)d * E_NUM);
        float4 a = w4[0], b = w4[1];
        acc[0] += xv * a.x; acc[1] += xv * a.y; acc[2] += xv * a.z; acc[3] += xv * a.w;
        acc[4] += xv * b.x; acc[5] += xv * b.y; acc[6] += xv * b.z; acc[7] += xv * b.w;
    }
#pragma unroll
    for (int off = 16; off > 0; off >>= 1)
#pragma unroll
        for (int e = 0; e < 8; e++)
            acc[e] += __shfl_down_sync(0xffffffffu, acc[e], off);
    if (lane == 0) {
        float lg[8];
#pragma unroll
        for (int e = 0; e < 8; e++) lg[e] = acc[e] + br[e];
        int e0 = 0;
#pragma unroll
        for (int e = 1; e < 8; e++) if (lg[e] > lg[e0]) e0 = e;
        int e1 = (e0 == 0) ? 1 : 0;
#pragma unroll
        for (int e = 0; e < 8; e++)
            if (e != e0 && e != e1 && lg[e] > lg[e1]) e1 = e;
        float z  = __expf(lg[e1] - lg[e0]);
        float w0 = 1.0f / (1.0f + z);
        float w1 = z * w0;
        int p0 = atomicAdd(&g_cnt[e0], 1);
        g_tok[e0 * CAP + p0] = warp;
        int p1 = atomicAdd(&g_cnt[e1], 1);
        g_tok[e1 * CAP + p1] = warp;
        g_tslot[2 * warp]     = e0 * CAP + p0;  g_tw[2 * warp]     = w0;
        g_tslot[2 * warp + 1] = e1 * CAP + p1;  g_tw[2 * warp + 1] = w1;
    }
}

__global__ void offsets_kernel() {
    if (threadIdx.x == 0 && blockIdx.x == 0) {
        int acc = 0;
#pragma unroll
        for (int e = 0; e < E_NUM; e++) { g_off[e] = acc; acc += g_cnt[e]; }
    }
}

// out[t] = w0 * y[slot0] + w1 * y[slot1]   (deterministic 2-way combine)
__global__ void combine_kernel(float* __restrict__ out) {
    int i = blockIdx.x * blockDim.x + threadIdx.x;   // 0 .. N_TOK*256-1
    int t = i >> 8;
    int j = (i & 255) << 2;
    int s0e = g_tslot[2 * t], s1e = g_tslot[2 * t + 1];
    float w0 = g_tw[2 * t], w1 = g_tw[2 * t + 1];
    size_t s0 = (size_t)g_off[s0e >> 13] + (s0e & (CAP - 1));
    size_t s1 = (size_t)g_off[s1e >> 13] + (s1e & (CAP - 1));
    float4 a = *(const float4*)(g_y + s0 * D_DIM + j);
    float4 b = *(const float4*)(g_y + s1 * D_DIM + j);
    float4 o;
    o.x = w0 * a.x + w1 * b.x;
    o.y = w0 * a.y + w1 * b.y;
    o.z = w0 * a.z + w1 * b.z;
    o.w = w0 * a.w + w1 * b.w;
    *(float4*)(out + (size_t)t * D_DIM + j) = o;
}

// ---------------- grouped GEMM via mma.sync (HMMA), bf16x3 ----------------
template <int PHASE, int KDIM, int NDIM>
__global__ __launch_bounds__(256, 1)
void moe_hmma(const __nv_bfloat16* __restrict__ Ahg, const __nv_bfloat16* __restrict__ Alg,
              const __nv_bfloat16* __restrict__ Bhg, const __nv_bfloat16* __restrict__ Blg,
              const float* __restrict__ bias) {
    constexpr int C = KDIM / TK;
    const int e  = blockIdx.z;
    const int Ne = g_cnt[e];
    const int m0 = blockIdx.x * TM;
    if (m0 >= Ne) return;
    const int n0 = blockIdx.y * TN;
    const int base = g_off[e];

    extern __shared__ __align__(128) char smem[];
    const uint32_t sb = smem_u32(smem);
    const int tid = threadIdx.x;

    // ---- load assignments: thread -> rows (tid>>2, +64), 16B seg (tid&3) ----
    const int r0 = tid >> 2;
    const int sg = (tid & 3) * 16;
    const char *a0h, *a0l, *a1h, *a1l;
    {
        int rr0 = min(m0 + r0, Ne - 1);
        int rr1 = min(m0 + r0 + 64, Ne - 1);
        size_t i0 = (PHASE == 1) ? (size_t)g_tok[e * CAP + rr0] : (size_t)(base + rr0);
        size_t i1 = (PHASE == 1) ? (size_t)g_tok[e * CAP + rr1] : (size_t)(base + rr1);
        a0h = (const char*)(Ahg + i0 * KDIM) + sg;
        a0l = (const char*)(Alg + i0 * KDIM) + sg;
        a1h = (const char*)(Ahg + i1 * KDIM) + sg;
        a1l = (const char*)(Alg + i1 * KDIM) + sg;
    }
    const size_t brow = (size_t)e * NDIM + n0 + r0;
    const char* b0h = (const char*)(Bhg + brow * KDIM) + sg;
    const char* b0l = (const char*)(Blg + brow * KDIM) + sg;
    const char* b1h = b0h + (size_t)64 * KDIM * 2;
    const char* b1l = b0l + (size_t)64 * KDIM * 2;
    const uint32_t d0 = (uint32_t)r0 * ROWB + sg;
    const uint32_t d1 = d0 + 64 * ROWB;

    auto issue = [&](int c) {
        uint32_t st = sb + (uint32_t)(c & 1) * STG;
        int cb = c * 64;   // bytes per chunk along K
        CP16(st + AH + d0, a0h + cb); CP16(st + AH + d1, a1h + cb);
        CP16(st + AL + d0, a0l + cb); CP16(st + AL + d1, a1l + cb);
        CP16(st + BH + d0, b0h + cb); CP16(st + BH + d1, b1h + cb);
        CP16(st + BL + d0, b0l + cb); CP16(st + BL + d1, b1l + cb);
        CP_COMMIT();
    };

    float acc[4][4][4];
#pragma unroll
    for (int i = 0; i < 4; i++)
#pragma unroll
        for (int j = 0; j < 4; j++)
#pragma unroll
            for (int k = 0; k < 4; k++) acc[i][j][k] = 0.0f;

    const int lane = tid & 31, wid = tid >> 5;
    const int wm = (wid & 1) * 64;        // warp M offset
    const int wn = (wid >> 1) * 32;       // warp N offset
    const uint32_t a_off = (uint32_t)(wm + (lane & 15)) * ROWB + (lane >> 4) * 16;
    const uint32_t b_off = (uint32_t)(wn + (lane & 7) + ((lane >> 4) & 1) * 8) * ROWB
                         + ((lane >> 3) & 1) * 16;

    issue(0);
    issue(1);

    for (int c = 0; c < C; c++) {
        if (c + 1 < C) asm volatile("cp.async.wait_group 1;" ::: "memory");
        else           asm volatile("cp.async.wait_group 0;" ::: "memory");
        __syncthreads();
        const uint32_t st = sb + (uint32_t)(c & 1) * STG;
#pragma unroll
        for (int kk = 0; kk < 2; kk++) {
            uint32_t ah[16], al[16], bh[8], bl[8];
#pragma unroll
            for (int tm = 0; tm < 4; tm++) {
                ldsm4(ah + tm * 4, st + AH + a_off + tm * 16 * ROWB + kk * 32);
                ldsm4(al + tm * 4, st + AL + a_off + tm * 16 * ROWB + kk * 32);
            }
            ldsm4(bh,     st + BH + b_off + kk * 32);
            ldsm4(bh + 4, st + BH + b_off + 16 * ROWB + kk * 32);
            ldsm4(bl,     st + BL + b_off + kk * 32);
            ldsm4(bl + 4, st + BL + b_off + 16 * ROWB + kk * 32);
#pragma unroll
            for (int tm = 0; tm < 4; tm++)
#pragma unroll
                for (int tn = 0; tn < 4; tn++) {
                    mma_bf16(acc[tm][tn], ah + tm * 4, bh + tn * 2);
                    mma_bf16(acc[tm][tn], ah + tm * 4, bl + tn * 2);
                    mma_bf16(acc[tm][tn], al + tm * 4, bh + tn * 2);
                }
        }
        __syncthreads();
        if (c + 2 < C) issue(c + 2);
    }

    // ---- epilogue ----
    const int lr_base  = wm + (lane >> 2);
    const int col_base = n0 + wn + 2 * (lane & 3);
    const float* bp = bias + (size_t)e * NDIM;
#pragma unroll
    for (int tm = 0; tm < 4; tm++) {
#pragma unroll
        for (int half = 0; half < 2; half++) {
            int gr = m0 + lr_base + tm * 16 + half * 8;
            if (gr < Ne) {
                size_t pr = (size_t)(base + gr);
#pragma unroll
                for (int tn = 0; tn < 4; tn++) {
                    int col = col_base + tn * 8;
                    float c0 = acc[tm][tn][half * 2 + 0] + __ldg(bp + col);
                    float c1 = acc[tm][tn][half * 2 + 1] + __ldg(bp + col + 1);
                    if (PHASE == 1) {
                        c0 = fmaxf(c0, 0.f);
                        c1 = fmaxf(c1, 0.f);
                        __nv_bfloat16 h0 = __float2bfloat16(c0);
                        __nv_bfloat16 h1 = __float2bfloat16(c1);
                        __nv_bfloat162 hp; hp.x = h0; hp.y = h1;
                        __nv_bfloat162 lp;
                        lp.x = __float2bfloat16(c0 - __bfloat162float(h0));
                        lp.y = __float2bfloat16(c1 - __bfloat162float(h1));
                        *(__nv_bfloat162*)(g_hh + pr * H_DIM + col) = hp;
                        *(__nv_bfloat162*)(g_hl + pr * H_DIM + col) = lp;
                    } else {
                        float2 o; o.x = c0; o.y = c1;
                        *(float2*)(g_y + pr * D_DIM + col) = o;
                    }
                }
            }
        }
    }
}

// ---------------- launch ----------------
extern "C" void kernel_launch(void* const* d_in, const int* in_sizes, int n_in,
                              void* d_out, int out_size) {
    const float* x  = (const float*)d_in[0];
    const float* Wr = (const float*)d_in[1];
    const float* br = (const float*)d_in[2];
    const float* W1 = (const float*)d_in[3];
    const float* b1 = (const float*)d_in[4];
    const float* W2 = (const float*)d_in[5];
    const float* b2 = (const float*)d_in[6];
    float* out = (float*)d_out;

    cudaFuncSetAttribute(moe_hmma<1, D_DIM, H_DIM>,
                         cudaFuncAttributeMaxDynamicSharedMemorySize, GEMM_SMEM);
    cudaFuncSetAttribute(moe_hmma<2, H_DIM, D_DIM>,
                         cudaFuncAttributeMaxDynamicSharedMemorySize, GEMM_SMEM);

    __nv_bfloat16 *xh, *xl, *hh, *hl, *B1h, *B1l, *B2h, *B2l;
    cudaGetSymbolAddress((void**)&xh,  g_xh);  cudaGetSymbolAddress((void**)&xl,  g_xl);
    cudaGetSymbolAddress((void**)&hh,  g_hh);  cudaGetSymbolAddress((void**)&hl,  g_hl);
    cudaGetSymbolAddress((void**)&B1h, g_B1h); cudaGetSymbolAddress((void**)&B1l, g_B1l);
    cudaGetSymbolAddress((void**)&B2h, g_B2h); cudaGetSymbolAddress((void**)&B2l, g_B2l);

    zero_cnt_kernel<<<1, 32>>>();
    cvt_x_kernel<<<1024, 256>>>(x);
    {   // W1: K=1024, N=4096 -> [E][4096][1024]
        dim3 g(D_DIM / 32, H_DIM / 32, E_NUM);
        pack_w_kernel<<<g, 256>>>(W1, B1h, B1l, D_DIM, H_DIM);
    }
    {   // W2: K=4096, N=1024 -> [E][1024][4096]
        dim3 g(H_DIM / 32, D_DIM / 32, E_NUM);
        pack_w_kernel<<<g, 256>>>(W2, B2h, B2l, H_DIM, D_DIM);
    }
    router_kernel<<<(N_TOK * 32 + 255) / 256, 256>>>(x, Wr, br);
    offsets_kernel<<<1, 32>>>();

    {   // GEMM1: gathered x [Ne,1024] @ W1^T-packed -> relu -> h (hi/lo)
        dim3 g(CAP / TM, H_DIM / TN, E_NUM);
        moe_hmma<1, D_DIM, H_DIM><<<g, 256, GEMM_SMEM>>>(xh, xl, B1h, B1l, b1);
    }
    {   // GEMM2: h [Ne,4096] @ W2^T-packed -> y (+b2)
        dim3 g(CAP / TM, D_DIM / TN, E_NUM);
        moe_hmma<2, H_DIM, D_DIM><<<g, 256, GEMM_SMEM>>>(hh, hl, B2h, B2l, b2);
    }
    combine_kernel<<<N_TOK, 256>>>(out);
}

// round 4
// speedup vs baseline: 2.5917x; 1.0276x over previous
#include <cuda_runtime.h>
#include <cuda_bf16.h>
#include <math.h>
#include <stdint.h>

#define N_TOK 8192
#define D_DIM 1024
#define E_NUM 8
#define H_DIM 4096
#define CAP   8192
#define PAIRS 16384

#define TM 128
#define TN 128
#define TK 32            // bf16 elems per k-chunk (64 bytes per row)
#define ROWB 80          // padded SMEM row bytes (64 data + 16 pad)
#define AH 0
#define AL 10240
#define BH 20480
#define BL 30720
#define STG 40960
#define NSTAGE 4
#define GEMM_SMEM (NSTAGE * STG)

// ---------------- device scratch ----------------
__device__ int   g_cnt[E_NUM];
__device__ int   g_off[E_NUM];
__device__ int   g_tok[E_NUM * CAP];
__device__ int   g_tslot[2 * N_TOK];   // e*CAP + p for each token's 2 experts
__device__ float g_tw  [2 * N_TOK];

__device__ __nv_bfloat16 g_xh[(size_t)N_TOK * D_DIM];
__device__ __nv_bfloat16 g_xl[(size_t)N_TOK * D_DIM];
__device__ __nv_bfloat16 g_hh[(size_t)PAIRS * H_DIM];
__device__ __nv_bfloat16 g_hl[(size_t)PAIRS * H_DIM];
__device__ float         g_y [(size_t)PAIRS * D_DIM];
// packed weights, [E][N][K] row-major bf16 (transposed from [E][K][N] fp32)
__device__ __nv_bfloat16 g_B1h[(size_t)E_NUM * H_DIM * D_DIM];
__device__ __nv_bfloat16 g_B1l[(size_t)E_NUM * H_DIM * D_DIM];
__device__ __nv_bfloat16 g_B2h[(size_t)E_NUM * D_DIM * H_DIM];
__device__ __nv_bfloat16 g_B2l[(size_t)E_NUM * D_DIM * H_DIM];

// ---------------- helpers ----------------
__device__ __forceinline__ uint32_t smem_u32(const void* p) {
    return (uint32_t)__cvta_generic_to_shared(p);
}
#define CP16(dst, src) \
    asm volatile("cp.async.cg.shared.global [%0], [%1], 16;" :: "r"(dst), "l"(src) : "memory")
#define CP_COMMIT() asm volatile("cp.async.commit_group;" ::: "memory")

__device__ __forceinline__ void ldsm4(uint32_t* r, uint32_t addr) {
    asm volatile("ldmatrix.sync.aligned.m8n8.x4.shared.b16 {%0,%1,%2,%3}, [%4];"
        : "=r"(r[0]), "=r"(r[1]), "=r"(r[2]), "=r"(r[3]) : "r"(addr));
}
__device__ __forceinline__ void mma_bf16(float* c, const uint32_t* a, const uint32_t* b) {
    asm volatile("mma.sync.aligned.m16n8k16.row.col.f32.bf16.bf16.f32 "
        "{%0,%1,%2,%3}, {%4,%5,%6,%7}, {%8,%9}, {%0,%1,%2,%3};"
        : "+f"(c[0]), "+f"(c[1]), "+f"(c[2]), "+f"(c[3])
        : "r"(a[0]), "r"(a[1]), "r"(a[2]), "r"(a[3]), "r"(b[0]), "r"(b[1]));
}

// ---------------- small kernels ----------------
__global__ void zero_cnt_kernel() {
    if (threadIdx.x < E_NUM) g_cnt[threadIdx.x] = 0;
}

__global__ void cvt_x_kernel(const float* __restrict__ x) {
    size_t stride = (size_t)gridDim.x * blockDim.x;
    size_t n = (size_t)N_TOK * D_DIM;
    for (size_t i = (size_t)blockIdx.x * blockDim.x + threadIdx.x; i < n; i += stride) {
        float v = x[i];
        __nv_bfloat16 h = __float2bfloat16(v);
        g_xh[i] = h;
        g_xl[i] = __float2bfloat16(v - __bfloat162float(h));
    }
}

// W[e][K][N] fp32 -> P[e][N][K] bf16 hi/lo (32x32 tile transpose)
__global__ __launch_bounds__(256)
void pack_w_kernel(const float* __restrict__ W, __nv_bfloat16* __restrict__ Ph,
                   __nv_bfloat16* __restrict__ Pl, int K, int N) {
    __shared__ float s[32][33];
    const int k0 = blockIdx.x * 32, n0 = blockIdx.y * 32, e = blockIdx.z;
    const int tid = threadIdx.x;
    const int kk = tid >> 5, nn = tid & 31;
#pragma unroll
    for (int i = 0; i < 4; i++)
        s[kk + i * 8][nn] = W[((size_t)e * K + k0 + kk + i * 8) * N + n0 + nn];
    __syncthreads();
    const int n_r = tid >> 4;          // 0..15
    const int kp  = (tid & 15) * 2;
#pragma unroll
    for (int i = 0; i < 2; i++) {
        int nr = n_r + i * 16;
        float v0 = s[kp][nr], v1 = s[kp + 1][nr];
        __nv_bfloat16 h0 = __float2bfloat16(v0), h1 = __float2bfloat16(v1);
        __nv_bfloat162 hp; hp.x = h0; hp.y = h1;
        __nv_bfloat162 lp;
        lp.x = __float2bfloat16(v0 - __bfloat162float(h0));
        lp.y = __float2bfloat16(v1 - __bfloat162float(h1));
        size_t o = ((size_t)e * N + n0 + nr) * K + k0 + kp;
        *(__nv_bfloat162*)(Ph + o) = hp;
        *(__nv_bfloat162*)(Pl + o) = lp;
    }
}

__global__ void router_kernel(const float* __restrict__ x,
                              const float* __restrict__ Wr,
                              const float* __restrict__ br) {
    int warp = (blockIdx.x * blockDim.x + threadIdx.x) >> 5;
    int lane = threadIdx.x & 31;
    if (warp >= N_TOK) return;
    const float* xr = x + (size_t)warp * D_DIM;
    float acc[8];
#pragma unroll
    for (int e = 0; e < 8; e++) acc[e] = 0.0f;
    for (int d = lane; d < D_DIM; d += 32) {
        float xv = xr[d];
        const float4* w4 = (const float4*)(Wr + (size_t)d * E_NUM);
        float4 a = w4[0], b = w4[1];
        acc[0] += xv * a.x; acc[1] += xv * a.y; acc[2] += xv * a.z; acc[3] += xv * a.w;
        acc[4] += xv * b.x; acc[5] += xv * b.y; acc[6] += xv * b.z; acc[7] += xv * b.w;
    }
#pragma unroll
    for (int off = 16; off > 0; off >>= 1)
#pragma unroll
        for (int e = 0; e < 8; e++)
            acc[e] += __shfl_down_sync(0xffffffffu, acc[e], off);
    if (lane == 0) {
        float lg[8];
#pragma unroll
        for (int e = 0; e < 8; e++) lg[e] = acc[e] + br[e];
        int e0 = 0;
#pragma unroll
        for (int e = 1; e < 8; e++) if (lg[e] > lg[e0]) e0 = e;
        int e1 = (e0 == 0) ? 1 : 0;
#pragma unroll
        for (int e = 0; e < 8; e++)
            if (e != e0 && e != e1 && lg[e] > lg[e1]) e1 = e;
        float z  = __expf(lg[e1] - lg[e0]);
        float w0 = 1.0f / (1.0f + z);
        float w1 = z * w0;
        int p0 = atomicAdd(&g_cnt[e0], 1);
        g_tok[e0 * CAP + p0] = warp;
        int p1 = atomicAdd(&g_cnt[e1], 1);
        g_tok[e1 * CAP + p1] = warp;
        g_tslot[2 * warp]     = e0 * CAP + p0;  g_tw[2 * warp]     = w0;
        g_tslot[2 * warp + 1] = e1 * CAP + p1;  g_tw[2 * warp + 1] = w1;
    }
}

__global__ void offsets_kernel() {
    if (threadIdx.x == 0 && blockIdx.x == 0) {
        int acc = 0;
#pragma unroll
        for (int e = 0; e < E_NUM; e++) { g_off[e] = acc; acc += g_cnt[e]; }
    }
}

// out[t] = w0 * y[slot0] + w1 * y[slot1]   (deterministic 2-way combine)
__global__ void combine_kernel(float* __restrict__ out) {
    int i = blockIdx.x * blockDim.x + threadIdx.x;   // 0 .. N_TOK*256-1
    int t = i >> 8;
    int j = (i & 255) << 2;
    int s0e = g_tslot[2 * t], s1e = g_tslot[2 * t + 1];
    float w0 = g_tw[2 * t], w1 = g_tw[2 * t + 1];
    size_t s0 = (size_t)g_off[s0e >> 13] + (s0e & (CAP - 1));
    size_t s1 = (size_t)g_off[s1e >> 13] + (s1e & (CAP - 1));
    float4 a = *(const float4*)(g_y + s0 * D_DIM + j);
    float4 b = *(const float4*)(g_y + s1 * D_DIM + j);
    float4 o;
    o.x = w0 * a.x + w1 * b.x;
    o.y = w0 * a.y + w1 * b.y;
    o.z = w0 * a.z + w1 * b.z;
    o.w = w0 * a.w + w1 * b.w;
    *(float4*)(out + (size_t)t * D_DIM + j) = o;
}

// ---------------- grouped GEMM via mma.sync (HMMA), bf16x3, 4-stage ----------------
template <int PHASE, int KDIM, int NDIM>
__global__ __launch_bounds__(256, 1)
void moe_hmma(const __nv_bfloat16* __restrict__ Ahg, const __nv_bfloat16* __restrict__ Alg,
              const __nv_bfloat16* __restrict__ Bhg, const __nv_bfloat16* __restrict__ Blg,
              const float* __restrict__ bias) {
    constexpr int C = KDIM / TK;
    const int e  = blockIdx.z;
    const int Ne = g_cnt[e];
    const int m0 = blockIdx.x * TM;
    if (m0 >= Ne) return;
    const int n0 = blockIdx.y * TN;
    const int base = g_off[e];

    extern __shared__ __align__(128) char smem[];
    const uint32_t sb = smem_u32(smem);
    const int tid = threadIdx.x;

    // ---- load assignments: thread -> rows (tid>>2, +64), 16B seg (tid&3) ----
    const int r0 = tid >> 2;
    const int sg = (tid & 3) * 16;
    const char *a0h, *a0l, *a1h, *a1l;
    {
        int rr0 = min(m0 + r0, Ne - 1);
        int rr1 = min(m0 + r0 + 64, Ne - 1);
        size_t i0 = (PHASE == 1) ? (size_t)g_tok[e * CAP + rr0] : (size_t)(base + rr0);
        size_t i1 = (PHASE == 1) ? (size_t)g_tok[e * CAP + rr1] : (size_t)(base + rr1);
        a0h = (const char*)(Ahg + i0 * KDIM) + sg;
        a0l = (const char*)(Alg + i0 * KDIM) + sg;
        a1h = (const char*)(Ahg + i1 * KDIM) + sg;
        a1l = (const char*)(Alg + i1 * KDIM) + sg;
    }
    const size_t brow = (size_t)e * NDIM + n0 + r0;
    const char* b0h = (const char*)(Bhg + brow * KDIM) + sg;
    const char* b0l = (const char*)(Blg + brow * KDIM) + sg;
    const char* b1h = b0h + (size_t)64 * KDIM * 2;
    const char* b1l = b0l + (size_t)64 * KDIM * 2;
    const uint32_t d0 = (uint32_t)r0 * ROWB + sg;
    const uint32_t d1 = d0 + 64 * ROWB;

    // exactly one commit group per call (empty near the tail) so the
    // outstanding-group count is constant and wait_group 2 is exact.
    auto issue = [&](int c) {
        if (c < C) {
            uint32_t st = sb + (uint32_t)(c & (NSTAGE - 1)) * STG;
            int cb = c * 64;   // bytes per chunk along K
            CP16(st + AH + d0, a0h + cb); CP16(st + AH + d1, a1h + cb);
            CP16(st + AL + d0, a0l + cb); CP16(st + AL + d1, a1l + cb);
            CP16(st + BH + d0, b0h + cb); CP16(st + BH + d1, b1h + cb);
            CP16(st + BL + d0, b0l + cb); CP16(st + BL + d1, b1l + cb);
        }
        CP_COMMIT();
    };

    float acc[4][4][4];
#pragma unroll
    for (int i = 0; i < 4; i++)
#pragma unroll
        for (int j = 0; j < 4; j++)
#pragma unroll
            for (int k = 0; k < 4; k++) acc[i][j][k] = 0.0f;

    const int lane = tid & 31, wid = tid >> 5;
    const int wm = (wid & 1) * 64;        // warp M offset
    const int wn = (wid >> 1) * 32;       // warp N offset
    const uint32_t a_off = (uint32_t)(wm + (lane & 15)) * ROWB + (lane >> 4) * 16;
    const uint32_t b_off = (uint32_t)(wn + (lane & 7) + ((lane >> 4) & 1) * 8) * ROWB
                         + ((lane >> 3) & 1) * 16;

    issue(0);
    issue(1);
    issue(2);

    for (int c = 0; c < C; c++) {
        asm volatile("cp.async.wait_group 2;" ::: "memory");
        __syncthreads();
        // stage (c-1)%4 == stage (c+3)%4 was fully consumed before this barrier,
        // so the refill for chunk c+3 can go out immediately.
        issue(c + 3);

        const uint32_t st = sb + (uint32_t)(c & (NSTAGE - 1)) * STG;
#pragma unroll
        for (int kk = 0; kk < 2; kk++) {
            uint32_t ah[16], al[16], bh[8], bl[8];
#pragma unroll
            for (int tm = 0; tm < 4; tm++) {
                ldsm4(ah + tm * 4, st + AH + a_off + tm * 16 * ROWB + kk * 32);
                ldsm4(al + tm * 4, st + AL + a_off + tm * 16 * ROWB + kk * 32);
            }
            ldsm4(bh,     st + BH + b_off + kk * 32);
            ldsm4(bh + 4, st + BH + b_off + 16 * ROWB + kk * 32);
            ldsm4(bl,     st + BL + b_off + kk * 32);
            ldsm4(bl + 4, st + BL + b_off + 16 * ROWB + kk * 32);
#pragma unroll
            for (int tm = 0; tm < 4; tm++)
#pragma unroll
                for (int tn = 0; tn < 4; tn++) {
                    mma_bf16(acc[tm][tn], ah + tm * 4, bh + tn * 2);
                    mma_bf16(acc[tm][tn], ah + tm * 4, bl + tn * 2);
                    mma_bf16(acc[tm][tn], al + tm * 4, bh + tn * 2);
                }
        }
    }

    // ---- epilogue ----
    const int lr_base  = wm + (lane >> 2);
    const int col_base = n0 + wn + 2 * (lane & 3);
    const float* bp = bias + (size_t)e * NDIM;
#pragma unroll
    for (int tm = 0; tm < 4; tm++) {
#pragma unroll
        for (int half = 0; half < 2; half++) {
            int gr = m0 + lr_base + tm * 16 + half * 8;
            if (gr < Ne) {
                size_t pr = (size_t)(base + gr);
#pragma unroll
                for (int tn = 0; tn < 4; tn++) {
                    int col = col_base + tn * 8;
                    float c0 = acc[tm][tn][half * 2 + 0] + __ldg(bp + col);
                    float c1 = acc[tm][tn][half * 2 + 1] + __ldg(bp + col + 1);
                    if (PHASE == 1) {
                        c0 = fmaxf(c0, 0.f);
                        c1 = fmaxf(c1, 0.f);
                        __nv_bfloat16 h0 = __float2bfloat16(c0);
                        __nv_bfloat16 h1 = __float2bfloat16(c1);
                        __nv_bfloat162 hp; hp.x = h0; hp.y = h1;
                        __nv_bfloat162 lp;
                        lp.x = __float2bfloat16(c0 - __bfloat162float(h0));
                        lp.y = __float2bfloat16(c1 - __bfloat162float(h1));
                        *(__nv_bfloat162*)(g_hh + pr * H_DIM + col) = hp;
                        *(__nv_bfloat162*)(g_hl + pr * H_DIM + col) = lp;
                    } else {
                        float2 o; o.x = c0; o.y = c1;
                        *(float2*)(g_y + pr * D_DIM + col) = o;
                    }
                }
            }
        }
    }
}

// ---------------- launch ----------------
extern "C" void kernel_launch(void* const* d_in, const int* in_sizes, int n_in,
                              void* d_out, int out_size) {
    const float* x  = (const float*)d_in[0];
    const float* Wr = (const float*)d_in[1];
    const float* br = (const float*)d_in[2];
    const float* W1 = (const float*)d_in[3];
    const float* b1 = (const float*)d_in[4];
    const float* W2 = (const float*)d_in[5];
    const float* b2 = (const float*)d_in[6];
    float* out = (float*)d_out;

    cudaFuncSetAttribute(moe_hmma<1, D_DIM, H_DIM>,
                         cudaFuncAttributeMaxDynamicSharedMemorySize, GEMM_SMEM);
    cudaFuncSetAttribute(moe_hmma<2, H_DIM, D_DIM>,
                         cudaFuncAttributeMaxDynamicSharedMemorySize, GEMM_SMEM);

    __nv_bfloat16 *xh, *xl, *hh, *hl, *B1h, *B1l, *B2h, *B2l;
    cudaGetSymbolAddress((void**)&xh,  g_xh);  cudaGetSymbolAddress((void**)&xl,  g_xl);
    cudaGetSymbolAddress((void**)&hh,  g_hh);  cudaGetSymbolAddress((void**)&hl,  g_hl);
    cudaGetSymbolAddress((void**)&B1h, g_B1h); cudaGetSymbolAddress((void**)&B1l, g_B1l);
    cudaGetSymbolAddress((void**)&B2h, g_B2h); cudaGetSymbolAddress((void**)&B2l, g_B2l);

    zero_cnt_kernel<<<1, 32>>>();
    cvt_x_kernel<<<1024, 256>>>(x);
    {   // W1: K=1024, N=4096 -> [E][4096][1024]
        dim3 g(D_DIM / 32, H_DIM / 32, E_NUM);
        pack_w_kernel<<<g, 256>>>(W1, B1h, B1l, D_DIM, H_DIM);
    }
    {   // W2: K=4096, N=1024 -> [E][1024][4096]
        dim3 g(H_DIM / 32, D_DIM / 32, E_NUM);
        pack_w_kernel<<<g, 256>>>(W2, B2h, B2l, H_DIM, D_DIM);
    }
    router_kernel<<<(N_TOK * 32 + 255) / 256, 256>>>(x, Wr, br);
    offsets_kernel<<<1, 32>>>();

    {   // GEMM1: gathered x [Ne,1024] @ W1^T-packed -> relu -> h (hi/lo)
        dim3 g(CAP / TM, H_DIM / TN, E_NUM);
        moe_hmma<1, D_DIM, H_DIM><<<g, 256, GEMM_SMEM>>>(xh, xl, B1h, B1l, b1);
    }
    {   // GEMM2: h [Ne,4096] @ W2^T-packed -> y (+b2)
        dim3 g(CAP / TM, D_DIM / TN, E_NUM);
        moe_hmma<2, H_DIM, D_DIM><<<g, 256, GEMM_SMEM>>>(hh, hl, B2h, B2l, b2);
    }
    combine_kernel<<<N_TOK, 256>>>(out);
}